// round 7
// baseline (speedup 1.0000x reference)
#include <cuda_runtime.h>
#include <cuda_bf16.h>
#include <cstdint>

// BispectrumCalculator: target [B=32, T=4, N=512] f32
//   y = fft(target);  Bx[k,l] = y[k]*conj(y[l])*y[(l-k)%N]
//   source[b,{re,im},k,l] = mean_t Bx;  out = concat(source, target)
//
// Real input => Bx[l,k] = conj(Bx[k,l]) (Hermitian): compute upper-triangle
// 64x64 tiles only; emit mirror tile via padded smem transpose.

#define B_DIM 32
#define T_DIM 4
#define N_DIM 512
#define NROWS (B_DIM * T_DIM)                           // 128
#define SRC_ELEMS ((size_t)B_DIM * 2 * N_DIM * N_DIM)   // 16,777,216
#define TGT_ELEMS (B_DIM * T_DIM * N_DIM)               // 65,536
#define TILE 64
#define NT (N_DIM / TILE)                               // 8
#define NTRI (NT * (NT + 1) / 2)                        // 36
#define NN (N_DIM * N_DIM)                              // 262,144 (fits int)

// FFT results, t-paired: g_y2[b][p][n] = float4(y_{2p}[n].re, y_{2p}[n].im,
//                                               y_{2p+1}[n].re, y_{2p+1}[n].im)
__device__ float4 g_y2[B_DIM * 2 * N_DIM];

// ---------------------------------------------------------------------------
// Kernel 1: 512-point radix-2 DIT FFT, one row per block, 256 threads.
//           Also copies the target tail into the output.
// ---------------------------------------------------------------------------
__global__ void fft512_kernel(const float* __restrict__ x,
                              float* __restrict__ out, int copy_tail) {
    __shared__ float2 s[N_DIM];
    const int row = blockIdx.x;          // 0..127
    const int tid = threadIdx.x;         // 0..255
    const float* xr = x + row * N_DIM;

    if (copy_tail && tid < 128) {        // 128 float4 = 512 floats per row
        ((float4*)(out + SRC_ELEMS + (size_t)row * N_DIM))[tid] =
            ((const float4*)xr)[tid];
    }

    #pragma unroll
    for (int i = tid; i < N_DIM; i += 256) {
        int r = __brev((unsigned)i) >> 23;   // 9-bit bit reversal
        s[r] = make_float2(xr[i], 0.0f);
    }
    __syncthreads();

    #pragma unroll
    for (int len = 2; len <= N_DIM; len <<= 1) {
        int half = len >> 1;
        int j    = tid & (half - 1);
        int grp  = tid / half;
        int base = grp * len;
        float ang = -6.283185307179586f * (float)j / (float)len;
        float wr, wi;
        __sincosf(ang, &wi, &wr);
        float2 a = s[base + j];
        float2 b = s[base + j + half];
        float tr = wr * b.x - wi * b.y;
        float ti = wr * b.y + wi * b.x;
        s[base + j]        = make_float2(a.x + tr, a.y + ti);
        s[base + j + half] = make_float2(a.x - tr, a.y - ti);
        __syncthreads();
    }

    // Paired store: row = b*4 + t -> half (t&1) of float4 at [b*2 + t/2][i]
    const int b = row >> 2, t = row & 3;
    float2* dst = (float2*)g_y2 + ((size_t)((b * 2 + (t >> 1)) * N_DIM)) * 2 + (t & 1);
    #pragma unroll
    for (int i = tid; i < N_DIM; i += 256)
        dst[i * 2] = s[i];
}

// ---------------------------------------------------------------------------
// Kernel 2: bispectrum on upper-triangle tiles.
//   grid = (32, 36)  (b fastest); block = 512 threads.
//   Dynamic smem: sy[2][512] float4 (16KB) + stre/stim[64][65] (33.3KB).
//   3 blocks/SM target: 42-reg budget, all addressing in 32-bit offsets.
// ---------------------------------------------------------------------------
__global__ __launch_bounds__(512, 3)
void bispec_kernel(float* __restrict__ out) {
    extern __shared__ float dsm[];
    float4* sy   = (float4*)dsm;          // 1024 float4
    float*  stre = dsm + 4096;            // 64*65 floats
    float*  stim = stre + 64 * 65;

    const int b   = blockIdx.x;
    const int tid = threadIdx.x;
    const int tx  = tid & 63;             // l within tile
    const int tyg = tid >> 6;             // 0..7, k sub-group

    // Triangle index -> (ti, tj), tj >= ti
    int q = blockIdx.y, ti = 0, span = NT;
    while (q >= span) { q -= span; span--; ti++; }
    const int tj = ti + q;
    const int K0 = ti * TILE;
    const int L0 = tj * TILE;

    // Load y tile-pair arrays (1024 float4 / 512 threads = 2 each)
    const float4* gy = g_y2 + b * (2 * N_DIM);
    sy[tid]       = gy[tid];
    sy[tid + 512] = gy[tid + 512];
    __syncthreads();

    const int l = L0 + tx;
    const float4 c01 = sy[l];             // conj side, t0/t1
    const float4 c23 = sy[N_DIM + l];     // conj side, t2/t3

    // 32-bit addressing: per-batch base, element offsets < 2^25
    float* out_b = out + (size_t)b * (2u * NN);

    #pragma unroll
    for (int kk = 0; kk < 8; kk++) {
        const int kloc = tyg * 8 + kk;
        const int k = K0 + kloc;
        const int m = (l - k) & (N_DIM - 1);

        float are, aim;
        {
            float4 A = sy[k];
            float4 D = sy[m];
            float pre = A.x * c01.x + A.y * c01.y;
            float pim = A.y * c01.x - A.x * c01.y;
            are = pre * D.x - pim * D.y;
            aim = pre * D.y + pim * D.x;
            pre = A.z * c01.z + A.w * c01.w;
            pim = A.w * c01.z - A.z * c01.w;
            are += pre * D.z - pim * D.w;
            aim += pre * D.w + pim * D.z;
        }
        {
            float4 A = sy[N_DIM + k];
            float4 D = sy[N_DIM + m];
            float pre = A.x * c23.x + A.y * c23.y;
            float pim = A.y * c23.x - A.x * c23.y;
            are += pre * D.x - pim * D.y;
            aim += pre * D.y + pim * D.x;
            pre = A.z * c23.z + A.w * c23.w;
            pim = A.w * c23.z - A.z * c23.w;
            are += pre * D.z - pim * D.w;
            aim += pre * D.w + pim * D.z;
        }
        are *= 0.25f;
        aim *= 0.25f;

        const unsigned o = (unsigned)(k * N_DIM + l);
        out_b[o]      = are;
        out_b[o + NN] = aim;
        stre[kloc * 65 + tx] = are;
        stim[kloc * 65 + tx] = aim;
    }

    if (ti == tj) return;                 // diagonal tile: no mirror

    __syncthreads();

    // Mirror tile: out[L0+r][K0+tx] = conj(Bx[K0+tx][L0+r])
    #pragma unroll
    for (int kk = 0; kk < 8; kk++) {
        const int r = tyg * 8 + kk;
        const float re = stre[tx * 65 + r];
        const float im = stim[tx * 65 + r];
        const unsigned o = (unsigned)((L0 + r) * N_DIM + (K0 + tx));
        out_b[o]      = re;
        out_b[o + NN] = -im;
    }
}

extern "C" void kernel_launch(void* const* d_in, const int* in_sizes, int n_in,
                              void* d_out, int out_size) {
    const float* target = (const float*)d_in[0];
    float* out = (float*)d_out;

    const int copy_tail = ((size_t)out_size >= SRC_ELEMS + TGT_ELEMS) ? 1 : 0;

    const int smem_bytes = (4096 + 2 * 64 * 65) * (int)sizeof(float);  // 49,664
    static bool attr_set = false;
    if (!attr_set) {
        cudaFuncSetAttribute(bispec_kernel,
                             cudaFuncAttributeMaxDynamicSharedMemorySize,
                             smem_bytes);
        attr_set = true;
    }

    fft512_kernel<<<NROWS, 256>>>(target, out, copy_tail);
    bispec_kernel<<<dim3(B_DIM, NTRI), 512, smem_bytes>>>(out);
}